// round 8
// baseline (speedup 1.0000x reference)
#include <cuda_runtime.h>

#define BATCH 8
#define HH 512
#define WW 512
#define W2 (WW / 2)
#define PLANE (HH * WW)
#define NP (BATCH * PLANE)
#define RAD 15
#define INV_K2 (1.0f / 961.0f)
#define EPSV 1e-6f
#define SEGV 32       // rows per vertical segment (k_vh, column-split)
#define SEG2 32       // rows per vertical segment (k_v2, column-split)
#define SPAD 544
#define PADI(i) ((i) + ((i) >> 4))

// -------- scratch (device globals) --------
// stage-1 quantities: 0=I, 1=I*I, 2..4=p_c, 5..7=I*p_c
__device__ float g_gray[NP];      // 8 MB
__device__ float g_hsum[8][NP];   // 64 MB
__device__ float g_hsum2[6][NP];  // 48 MB

__device__ __forceinline__ float iscan(float v, int lane) {
#pragma unroll
    for (int o = 1; o < 32; o <<= 1) {
        float n = __shfl_up_sync(0xffffffffu, v, o);
        if (lane >= o) v += n;
    }
    return v;
}

// ============================================================================
// K1: horizontal pass, chunk-local scan, register-direct loads (R6 config —
// proven at the ~24.6us plateau across 4 variants). 1 warp/row, 4 rows/block.
// ============================================================================
__global__ __launch_bounds__(128) void k_h1(const float* __restrict__ guide,
                                            const float* __restrict__ input) {
    const int warp = threadIdx.x >> 5;
    const int lane = threadIdx.x & 31;
    const int grow = blockIdx.x * 4 + warp;
    const int b = grow >> 9;
    const int r = grow & 511;

    const float* gR = guide + ((size_t)(b * 3 + 0) * HH + r) * WW;
    const float* gG = guide + ((size_t)(b * 3 + 1) * HH + r) * WW;
    const float* gB = guide + ((size_t)(b * 3 + 2) * HH + r) * WW;
    const float* p0 = input + ((size_t)(b * 3 + 0) * HH + r) * WW;
    const float* p1 = input + ((size_t)(b * 3 + 1) * HH + r) * WW;
    const float* p2 = input + ((size_t)(b * 3 + 2) * HH + r) * WW;

    __shared__ float sp[4][SPAD];
    float* pref = sp[warp];

    const size_t rowOff = (size_t)grow * WW;
    const int cb = lane * 16;

    float gv[16], pv[16], lp[16];

#pragma unroll
    for (int j = 0; j < 4; j++) {
        float4 rv = ((const float4*)(gR + cb))[j];
        float4 gg = ((const float4*)(gG + cb))[j];
        float4 bv = ((const float4*)(gB + cb))[j];
        gv[4*j+0] = 0.299f * rv.x + 0.587f * gg.x + 0.114f * bv.x;
        gv[4*j+1] = 0.299f * rv.y + 0.587f * gg.y + 0.114f * bv.y;
        gv[4*j+2] = 0.299f * rv.z + 0.587f * gg.z + 0.114f * bv.z;
        gv[4*j+3] = 0.299f * rv.w + 0.587f * gg.w + 0.114f * bv.w;
    }
#pragma unroll
    for (int j = 0; j < 4; j++) {
        float4 o;
        o.x = gv[4*j+0]; o.y = gv[4*j+1]; o.z = gv[4*j+2]; o.w = gv[4*j+3];
        ((float4*)(g_gray + rowOff + cb))[j] = o;
    }

    auto scan_store = [&](float* __restrict__ outp) {
        float tot = lp[15];
        float ex = iscan(tot, lane) - tot;
#pragma unroll
        for (int k = 0; k < 16; k++) pref[PADI(cb + k)] = ex + lp[k];
        __syncwarp();
#pragma unroll
        for (int i = 0; i < 16; i++) {
            int x = i * 32 + lane;
            int hx = (x + RAD > WW - 1) ? (WW - 1) : (x + RAD);
            float hi = pref[PADI(hx)];
            float lo = (x >= RAD + 1) ? pref[PADI(x - RAD - 1)] : 0.f;
            outp[x] = hi - lo;
        }
        __syncwarp();
    };

    { float a = 0.f;
#pragma unroll
      for (int k = 0; k < 16; k++) { a += gv[k]; lp[k] = a; } }
    scan_store(g_hsum[0] + rowOff);
    { float a = 0.f;
#pragma unroll
      for (int k = 0; k < 16; k++) { a += gv[k] * gv[k]; lp[k] = a; } }
    scan_store(g_hsum[1] + rowOff);

    const float* pc[3] = { p0, p1, p2 };
    const int qp[3] = { 2, 3, 4 };
    const int qip[3] = { 5, 6, 7 };
#pragma unroll
    for (int c = 0; c < 3; c++) {
#pragma unroll
        for (int j = 0; j < 4; j++) {
            float4 v = ((const float4*)(pc[c] + cb))[j];
            pv[4*j+0] = v.x; pv[4*j+1] = v.y; pv[4*j+2] = v.z; pv[4*j+3] = v.w;
        }
        { float a = 0.f;
#pragma unroll
          for (int k = 0; k < 16; k++) { a += pv[k]; lp[k] = a; } }
        scan_store(g_hsum[qp[c]] + rowOff);
        { float a = 0.f;
#pragma unroll
          for (int k = 0; k < 16; k++) { a += gv[k] * pv[k]; lp[k] = a; } }
        scan_store(g_hsum[qip[c]] + rowOff);
    }
}

// ============================================================================
// K2 (fused vertical+horizontal on a,b) — COLUMN-SPLIT with apron.
// Block: 288 threads = window of 288 cols (256 owned + 16 apron each side),
// SEGV=32 rows. Box sums are local -> block scan over the window suffices.
// grid (2 halves, HH/SEGV, BATCH) = (2, 16, 8) = 256 blocks, 9 warps each.
// ============================================================================
__global__ __launch_bounds__(288) void k_vh() {
    const int t    = threadIdx.x;        // window slot 0..287
    const int warp = t >> 5;             // 0..8
    const int lane = t & 31;
    const int h  = blockIdx.x;           // column half (0 or 1)
    const int r0 = blockIdx.y * SEGV;
    const int b  = blockIdx.z;
    const int c0 = h * 256;
    const int ws = c0 - 16;              // window start (may be -16)
    const int wc = ws + t;               // this thread's global column
    const bool valid = (wc >= 0) && (wc < WW);
    const int bbase = b * PLANE;

    __shared__ float s_pref[2][6][288];  // 13.5 KB
    __shared__ float s_wtot[2][6][9];

    float s[8];
#pragma unroll
    for (int q = 0; q < 8; q++) s[q] = 0.f;

    const int jstart = (r0 - RAD < 0) ? 0 : (r0 - RAD);
    if (valid) {
#pragma unroll 4
        for (int j = jstart; j <= r0 + RAD; j++) {
            const int off = bbase + j * WW + wc;
#pragma unroll
            for (int q = 0; q < 8; q++) s[q] += g_hsum[q][off];
        }
    }

    for (int i = 0; i < SEGV; i++) {
        const int row = r0 + i;
        const int bu = i & 1;

        // ---- prefetch next slide loads ----
        const int lead  = row + RAD + 1;
        const int trail = row - RAD;
        const bool hl = valid && (lead < HH);
        const bool ht = valid && (trail >= 0);
        float ldv[8], trv[8];
        if (hl) {
            const int lo = bbase + lead * WW + wc;
#pragma unroll
            for (int q = 0; q < 8; q++) ldv[q] = g_hsum[q][lo];
        }
        if (ht) {
            const int to = bbase + trail * WW + wc;
#pragma unroll
            for (int q = 0; q < 8; q++) trv[q] = g_hsum[q][to];
        }

        // ---- a,b (invalid threads: s==0 -> a=b=0, contribute zeros) ----
        float ab[6];
        {
            float mI = s[0] * INV_K2;
            float cI = s[1] * INV_K2;
            float iv = 1.f / (cI - mI * mI + EPSV);
#pragma unroll
            for (int c = 0; c < 3; c++) {
                float mp  = s[2 + c] * INV_K2;
                float cIp = s[5 + c] * INV_K2;
                float a   = (cIp - mI * mp) * iv;
                ab[c]     = a;
                ab[3 + c] = mp - a * mI;
            }
        }

        // ---- block scan over the 288-wide window (2 barriers) ----
        float wv[6];
#pragma unroll
        for (int q = 0; q < 6; q++) {
            wv[q] = iscan(ab[q], lane);
            if (lane == 31) s_wtot[bu][q][warp] = wv[q];
        }
        __syncthreads();
#pragma unroll
        for (int q = 0; q < 6; q++) {
            float carry = 0.f;
#pragma unroll
            for (int w = 0; w < 8; w++) if (w < warp) carry += s_wtot[bu][q][w];
            s_pref[bu][q][t] = carry + wv[q];
        }
        __syncthreads();

        // ---- horizontal box sums for owned cols (threads 16..271) ----
        if (t >= 16 && t < 272) {
            const int x = wc;                       // owned col c0..c0+255
            int hiIdx = t + RAD;
            const int maxIdx = (WW - 1) - ws;       // local idx of col 511
            if (hiIdx > maxIdx) hiIdx = maxIdx;
            const bool hasLo = (x >= RAD + 1);
            const int loIdx = t - RAD - 1;
            const int off = bbase + row * WW + x;
#pragma unroll
            for (int q = 0; q < 6; q++) {
                float hi = s_pref[bu][q][hiIdx];
                float lo = hasLo ? s_pref[bu][q][loIdx] : 0.f;
                g_hsum2[q][off] = hi - lo;
            }
        }

        // ---- apply slide ----
        if (hl) {
#pragma unroll
            for (int q = 0; q < 8; q++) s[q] += ldv[q];
        }
        if (ht) {
#pragma unroll
            for (int q = 0; q < 8; q++) s[q] -= trv[q];
        }
    }
}

// ============================================================================
// K3: vertical running sums on hsum2, COLUMN-SPLIT (no scan -> trivial split).
// Block: 128 threads x float2 = 256 cols, SEG2=32 rows, per channel.
// grid (2, HH/SEG2, BATCH*3) = (2, 16, 24) = 768 blocks.
// ============================================================================
__global__ __launch_bounds__(128) void k_v2(float* __restrict__ out) {
    const int t  = blockIdx.x * 128 + threadIdx.x;   // float2 col index 0..255
    const int zc = blockIdx.z;
    const int b  = zc / 3;
    const int c  = zc - b * 3;
    const int r0 = blockIdx.y * SEG2;
    const int base = b * (PLANE / 2) + t;

    const float2* __restrict__ pa = (const float2*)g_hsum2[c];
    const float2* __restrict__ pb = (const float2*)g_hsum2[3 + c];
    const float2* __restrict__ pg = (const float2*)g_gray;
    float2* __restrict__ po = (float2*)(out + (size_t)zc * PLANE);

    float2 sa = make_float2(0.f, 0.f);
    float2 sb = make_float2(0.f, 0.f);

    const int jstart = (r0 - RAD < 0) ? 0 : (r0 - RAD);
#pragma unroll 4
    for (int j = jstart; j <= r0 + RAD; j++) {
        const int off = base + j * W2;
        float2 va = pa[off], vb = pb[off];
        sa.x += va.x; sa.y += va.y;
        sb.x += vb.x; sb.y += vb.y;
    }

#pragma unroll 4
    for (int i = 0; i < SEG2; i++) {
        const int row = r0 + i;
        const int off = base + row * W2;

        const int lead  = row + RAD + 1;
        const int trail = row - RAD;
        const bool hl = lead < HH;
        const bool ht = trail >= 0;
        float2 la, lb, ta, tb;
        if (hl) {
            const int lo = base + lead * W2;
            la = pa[lo]; lb = pb[lo];
        }
        if (ht) {
            const int to = base + trail * W2;
            ta = pa[to]; tb = pb[to];
        }

        const float2 gr = pg[off];
        float2 o;
        o.x = (sa.x * INV_K2) * gr.x + sb.x * INV_K2;
        o.y = (sa.y * INV_K2) * gr.y + sb.y * INV_K2;
        po[row * W2 + t] = o;

        if (hl) {
            sa.x += la.x; sa.y += la.y;
            sb.x += lb.x; sb.y += lb.y;
        }
        if (ht) {
            sa.x -= ta.x; sa.y -= ta.y;
            sb.x -= tb.x; sb.y -= tb.y;
        }
    }
}

// ============================================================================
extern "C" void kernel_launch(void* const* d_in, const int* in_sizes, int n_in,
                              void* d_out, int out_size) {
    const float* guide = (const float*)d_in[0];
    const float* input = (const float*)d_in[1];
    float* out = (float*)d_out;

    k_h1<<<BATCH * HH / 4, 128>>>(guide, input);
    k_vh<<<dim3(2, HH / SEGV, BATCH), 288>>>();
    k_v2<<<dim3(2, HH / SEG2, BATCH * 3), 128>>>(out);
}

// round 9
// speedup vs baseline: 1.0971x; 1.0971x over previous
#include <cuda_runtime.h>

#define BATCH 8
#define HH 512
#define WW 512
#define W2 (WW / 2)
#define W4 (WW / 4)
#define PLANE (HH * WW)
#define NP (BATCH * PLANE)
#define RAD 15
#define INV_K2 (1.0f / 961.0f)
#define EPSV 1e-6f
#define SEG 16        // rows per vertical segment (k_v2)  [R6 config]
#define SEGV 16       // rows per vertical segment (k_vh)  [chain length held at 16]
#define SPAD 544
#define PADI(i) ((i) + ((i) >> 4))

// -------- scratch (device globals) --------
// stage-1 quantities: 0=I, 1=I*I, 2..4=p_c, 5..7=I*p_c
__device__ float g_gray[NP];      // 8 MB
__device__ float g_hsum[8][NP];   // 64 MB
__device__ float g_hsum2[6][NP];  // 48 MB

__device__ __forceinline__ float iscan(float v, int lane) {
#pragma unroll
    for (int o = 1; o < 32; o <<= 1) {
        float n = __shfl_up_sync(0xffffffffu, v, o);
        if (lane >= o) v += n;
    }
    return v;
}

// ============================================================================
// K1: horizontal pass, chunk-local scan, register-direct loads (R6 config,
// pinned at ~24.6us = near its DRAM floor). 1 warp/row, 4 rows/block.
// ============================================================================
__global__ __launch_bounds__(128) void k_h1(const float* __restrict__ guide,
                                            const float* __restrict__ input) {
    const int warp = threadIdx.x >> 5;
    const int lane = threadIdx.x & 31;
    const int grow = blockIdx.x * 4 + warp;
    const int b = grow >> 9;
    const int r = grow & 511;

    const float* gR = guide + ((size_t)(b * 3 + 0) * HH + r) * WW;
    const float* gG = guide + ((size_t)(b * 3 + 1) * HH + r) * WW;
    const float* gB = guide + ((size_t)(b * 3 + 2) * HH + r) * WW;
    const float* p0 = input + ((size_t)(b * 3 + 0) * HH + r) * WW;
    const float* p1 = input + ((size_t)(b * 3 + 1) * HH + r) * WW;
    const float* p2 = input + ((size_t)(b * 3 + 2) * HH + r) * WW;

    __shared__ float sp[4][SPAD];
    float* pref = sp[warp];

    const size_t rowOff = (size_t)grow * WW;
    const int cb = lane * 16;

    float gv[16], pv[16], lp[16];

#pragma unroll
    for (int j = 0; j < 4; j++) {
        float4 rv = ((const float4*)(gR + cb))[j];
        float4 gg = ((const float4*)(gG + cb))[j];
        float4 bv = ((const float4*)(gB + cb))[j];
        gv[4*j+0] = 0.299f * rv.x + 0.587f * gg.x + 0.114f * bv.x;
        gv[4*j+1] = 0.299f * rv.y + 0.587f * gg.y + 0.114f * bv.y;
        gv[4*j+2] = 0.299f * rv.z + 0.587f * gg.z + 0.114f * bv.z;
        gv[4*j+3] = 0.299f * rv.w + 0.587f * gg.w + 0.114f * bv.w;
    }
#pragma unroll
    for (int j = 0; j < 4; j++) {
        float4 o;
        o.x = gv[4*j+0]; o.y = gv[4*j+1]; o.z = gv[4*j+2]; o.w = gv[4*j+3];
        ((float4*)(g_gray + rowOff + cb))[j] = o;
    }

    auto scan_store = [&](float* __restrict__ outp) {
        float tot = lp[15];
        float ex = iscan(tot, lane) - tot;
#pragma unroll
        for (int k = 0; k < 16; k++) pref[PADI(cb + k)] = ex + lp[k];
        __syncwarp();
#pragma unroll
        for (int i = 0; i < 16; i++) {
            int x = i * 32 + lane;
            int hx = (x + RAD > WW - 1) ? (WW - 1) : (x + RAD);
            float hi = pref[PADI(hx)];
            float lo = (x >= RAD + 1) ? pref[PADI(x - RAD - 1)] : 0.f;
            outp[x] = hi - lo;
        }
        __syncwarp();
    };

    { float a = 0.f;
#pragma unroll
      for (int k = 0; k < 16; k++) { a += gv[k]; lp[k] = a; } }
    scan_store(g_hsum[0] + rowOff);
    { float a = 0.f;
#pragma unroll
      for (int k = 0; k < 16; k++) { a += gv[k] * gv[k]; lp[k] = a; } }
    scan_store(g_hsum[1] + rowOff);

    const float* pc[3] = { p0, p1, p2 };
    const int qp[3] = { 2, 3, 4 };
    const int qip[3] = { 5, 6, 7 };
#pragma unroll
    for (int c = 0; c < 3; c++) {
#pragma unroll
        for (int j = 0; j < 4; j++) {
            float4 v = ((const float4*)(pc[c] + cb))[j];
            pv[4*j+0] = v.x; pv[4*j+1] = v.y; pv[4*j+2] = v.z; pv[4*j+3] = v.w;
        }
        { float a = 0.f;
#pragma unroll
          for (int k = 0; k < 16; k++) { a += pv[k]; lp[k] = a; } }
        scan_store(g_hsum[qp[c]] + rowOff);
        { float a = 0.f;
#pragma unroll
          for (int k = 0; k < 16; k++) { a += gv[k] * pv[k]; lp[k] = a; } }
        scan_store(g_hsum[qip[c]] + rowOff);
    }
}

// ============================================================================
// K2 (fused vertical+horizontal on a,b) — COLUMN-SPLIT, SEGV=16.
// Block: 288 threads = 256 owned cols + 16 apron each side; 16-row chain
// (same as proven R6 chain length), 2 barriers/row, slide prefetch.
// grid (2, HH/SEGV, BATCH) = (2, 32, 8) = 512 blocks, 9 warps each.
// ============================================================================
__global__ __launch_bounds__(288) void k_vh() {
    const int t    = threadIdx.x;        // window slot 0..287
    const int warp = t >> 5;             // 0..8
    const int lane = t & 31;
    const int h  = blockIdx.x;           // column half (0 or 1)
    const int r0 = blockIdx.y * SEGV;
    const int b  = blockIdx.z;
    const int c0 = h * 256;
    const int ws = c0 - 16;              // window start (may be -16)
    const int wc = ws + t;               // this thread's global column
    const bool valid = (wc >= 0) && (wc < WW);
    const int bbase = b * PLANE;

    __shared__ float s_pref[2][6][288];  // 13.5 KB
    __shared__ float s_wtot[2][6][9];

    float s[8];
#pragma unroll
    for (int q = 0; q < 8; q++) s[q] = 0.f;

    const int jstart = (r0 - RAD < 0) ? 0 : (r0 - RAD);
    if (valid) {
#pragma unroll 4
        for (int j = jstart; j <= r0 + RAD; j++) {
            const int off = bbase + j * WW + wc;
#pragma unroll
            for (int q = 0; q < 8; q++) s[q] += g_hsum[q][off];
        }
    }

    for (int i = 0; i < SEGV; i++) {
        const int row = r0 + i;
        const int bu = i & 1;

        // ---- prefetch next slide loads ----
        const int lead  = row + RAD + 1;
        const int trail = row - RAD;
        const bool hl = valid && (lead < HH);
        const bool ht = valid && (trail >= 0);
        float ldv[8], trv[8];
        if (hl) {
            const int lo = bbase + lead * WW + wc;
#pragma unroll
            for (int q = 0; q < 8; q++) ldv[q] = g_hsum[q][lo];
        }
        if (ht) {
            const int to = bbase + trail * WW + wc;
#pragma unroll
            for (int q = 0; q < 8; q++) trv[q] = g_hsum[q][to];
        }

        // ---- a,b (invalid threads carry zeros) ----
        float ab[6];
        {
            float mI = s[0] * INV_K2;
            float cI = s[1] * INV_K2;
            float iv = 1.f / (cI - mI * mI + EPSV);
#pragma unroll
            for (int c = 0; c < 3; c++) {
                float mp  = s[2 + c] * INV_K2;
                float cIp = s[5 + c] * INV_K2;
                float a   = (cIp - mI * mp) * iv;
                ab[c]     = a;
                ab[3 + c] = mp - a * mI;
            }
        }

        // ---- block scan over the 288-wide window (2 barriers) ----
        float wv[6];
#pragma unroll
        for (int q = 0; q < 6; q++) {
            wv[q] = iscan(ab[q], lane);
            if (lane == 31) s_wtot[bu][q][warp] = wv[q];
        }
        __syncthreads();
#pragma unroll
        for (int q = 0; q < 6; q++) {
            float carry = 0.f;
#pragma unroll
            for (int w = 0; w < 8; w++) if (w < warp) carry += s_wtot[bu][q][w];
            s_pref[bu][q][t] = carry + wv[q];
        }
        __syncthreads();

        // ---- horizontal box sums for owned cols (threads 16..271) ----
        if (t >= 16 && t < 272) {
            const int x = wc;
            int hiIdx = t + RAD;
            const int maxIdx = (WW - 1) - ws;       // local idx of col 511
            if (hiIdx > maxIdx) hiIdx = maxIdx;
            const bool hasLo = (x >= RAD + 1);
            const int loIdx = t - RAD - 1;
            const int off = bbase + row * WW + x;
#pragma unroll
            for (int q = 0; q < 6; q++) {
                float hi = s_pref[bu][q][hiIdx];
                float lo = hasLo ? s_pref[bu][q][loIdx] : 0.f;
                g_hsum2[q][off] = hi - lo;
            }
        }

        // ---- apply slide ----
        if (hl) {
#pragma unroll
            for (int q = 0; q < 8; q++) s[q] += ldv[q];
        }
        if (ht) {
#pragma unroll
            for (int q = 0; q < 8; q++) s[q] -= trv[q];
        }
    }
}

// ============================================================================
// K3: vertical running sums on hsum2 (float4/thread), per channel, fused
// output. [R6 config] grid (1, HH/SEG, BATCH*3) = 768 blocks.
// ============================================================================
__global__ __launch_bounds__(128) void k_v2(float* __restrict__ out) {
    const int t  = threadIdx.x;
    const int zc = blockIdx.z;
    const int b  = zc / 3;
    const int c  = zc - b * 3;
    const int r0 = blockIdx.y * SEG;
    const size_t base = (size_t)b * (PLANE / 4) + t;

    const float4* __restrict__ pa = (const float4*)g_hsum2[c];
    const float4* __restrict__ pb = (const float4*)g_hsum2[3 + c];
    const float4* __restrict__ pg = (const float4*)g_gray;
    float4* __restrict__ po = (float4*)(out + (size_t)zc * PLANE);

    float4 sa = make_float4(0.f, 0.f, 0.f, 0.f);
    float4 sb = make_float4(0.f, 0.f, 0.f, 0.f);

    const int jstart = (r0 - RAD < 0) ? 0 : (r0 - RAD);
#pragma unroll 4
    for (int j = jstart; j <= r0 + RAD; j++) {
        const size_t off = base + (size_t)j * W4;
        float4 va = pa[off], vb = pb[off];
        sa.x += va.x; sa.y += va.y; sa.z += va.z; sa.w += va.w;
        sb.x += vb.x; sb.y += vb.y; sb.z += vb.z; sb.w += vb.w;
    }

#pragma unroll 4
    for (int i = 0; i < SEG; i++) {
        const int row = r0 + i;
        const size_t off = base + (size_t)row * W4;

        const int lead  = row + RAD + 1;
        const int trail = row - RAD;
        const bool hl = lead < HH;
        const bool ht = trail >= 0;
        float4 la, lb, ta, tb;
        if (hl) {
            const size_t lo = base + (size_t)lead * W4;
            la = pa[lo]; lb = pb[lo];
        }
        if (ht) {
            const size_t to = base + (size_t)trail * W4;
            ta = pa[to]; tb = pb[to];
        }

        const float4 gr = pg[off];
        float4 o;
        o.x = (sa.x * INV_K2) * gr.x + sb.x * INV_K2;
        o.y = (sa.y * INV_K2) * gr.y + sb.y * INV_K2;
        o.z = (sa.z * INV_K2) * gr.z + sb.z * INV_K2;
        o.w = (sa.w * INV_K2) * gr.w + sb.w * INV_K2;
        po[(size_t)row * W4 + t] = o;

        if (hl) {
            sa.x += la.x; sa.y += la.y; sa.z += la.z; sa.w += la.w;
            sb.x += lb.x; sb.y += lb.y; sb.z += lb.z; sb.w += lb.w;
        }
        if (ht) {
            sa.x -= ta.x; sa.y -= ta.y; sa.z -= ta.z; sa.w -= ta.w;
            sb.x -= tb.x; sb.y -= tb.y; sb.z -= tb.z; sb.w -= tb.w;
        }
    }
}

// ============================================================================
extern "C" void kernel_launch(void* const* d_in, const int* in_sizes, int n_in,
                              void* d_out, int out_size) {
    const float* guide = (const float*)d_in[0];
    const float* input = (const float*)d_in[1];
    float* out = (float*)d_out;

    k_h1<<<BATCH * HH / 4, 128>>>(guide, input);
    k_vh<<<dim3(2, HH / SEGV, BATCH), 288>>>();
    k_v2<<<dim3(1, HH / SEG, BATCH * 3), 128>>>(out);
}

// round 10
// speedup vs baseline: 1.2041x; 1.0975x over previous
#include <cuda_runtime.h>

#define BATCH 8
#define HH 512
#define WW 512
#define W2 (WW / 2)
#define W4 (WW / 4)
#define PLANE (HH * WW)
#define NP (BATCH * PLANE)
#define RAD 15
#define INV_K2 (1.0f / 961.0f)
#define EPSV 1e-6f
#define SEG 16        // rows per vertical segment (k_v2)  [R6 config]
#define SEGV 8        // rows per vertical segment (k_vh)  [chain halved, blocks doubled]
#define SPAD 544
#define PADI(i) ((i) + ((i) >> 4))

// -------- scratch (device globals) --------
// stage-1 quantities: 0=I, 1=I*I, 2..4=p_c, 5..7=I*p_c
__device__ float g_gray[NP];      // 8 MB
__device__ float g_hsum[8][NP];   // 64 MB
__device__ float g_hsum2[6][NP];  // 48 MB

__device__ __forceinline__ float iscan(float v, int lane) {
#pragma unroll
    for (int o = 1; o < 32; o <<= 1) {
        float n = __shfl_up_sync(0xffffffffu, v, o);
        if (lane >= o) v += n;
    }
    return v;
}

// ============================================================================
// K1: horizontal pass, chunk-local scan, register-direct loads.
// NEW: box sums computed for the thread's OWN 16-col chunk and stored as
// 4x float4 (ST.128) instead of 16 strided ST.32. 1 warp/row, 4 rows/block.
// ============================================================================
__global__ __launch_bounds__(128) void k_h1(const float* __restrict__ guide,
                                            const float* __restrict__ input) {
    const int warp = threadIdx.x >> 5;
    const int lane = threadIdx.x & 31;
    const int grow = blockIdx.x * 4 + warp;
    const int b = grow >> 9;
    const int r = grow & 511;

    const float* gR = guide + ((size_t)(b * 3 + 0) * HH + r) * WW;
    const float* gG = guide + ((size_t)(b * 3 + 1) * HH + r) * WW;
    const float* gB = guide + ((size_t)(b * 3 + 2) * HH + r) * WW;
    const float* p0 = input + ((size_t)(b * 3 + 0) * HH + r) * WW;
    const float* p1 = input + ((size_t)(b * 3 + 1) * HH + r) * WW;
    const float* p2 = input + ((size_t)(b * 3 + 2) * HH + r) * WW;

    __shared__ float sp[4][SPAD];
    float* pref = sp[warp];

    const size_t rowOff = (size_t)grow * WW;
    const int cb = lane * 16;

    float gv[16], pv[16], lp[16];

#pragma unroll
    for (int j = 0; j < 4; j++) {
        float4 rv = ((const float4*)(gR + cb))[j];
        float4 gg = ((const float4*)(gG + cb))[j];
        float4 bv = ((const float4*)(gB + cb))[j];
        gv[4*j+0] = 0.299f * rv.x + 0.587f * gg.x + 0.114f * bv.x;
        gv[4*j+1] = 0.299f * rv.y + 0.587f * gg.y + 0.114f * bv.y;
        gv[4*j+2] = 0.299f * rv.z + 0.587f * gg.z + 0.114f * bv.z;
        gv[4*j+3] = 0.299f * rv.w + 0.587f * gg.w + 0.114f * bv.w;
    }
#pragma unroll
    for (int j = 0; j < 4; j++) {
        float4 o;
        o.x = gv[4*j+0]; o.y = gv[4*j+1]; o.z = gv[4*j+2]; o.w = gv[4*j+3];
        ((float4*)(g_gray + rowOff + cb))[j] = o;
    }

    auto scan_store = [&](float* __restrict__ outp) {
        float tot = lp[15];
        float ex = iscan(tot, lane) - tot;
#pragma unroll
        for (int k = 0; k < 16; k++) pref[PADI(cb + k)] = ex + lp[k];
        __syncwarp();
        // box sums for this thread's own 16 columns, vector stores
        float bx[16];
#pragma unroll
        for (int k = 0; k < 16; k++) {
            int x = cb + k;
            int hx = (x + RAD > WW - 1) ? (WW - 1) : (x + RAD);
            float hi = pref[PADI(hx)];
            float lo = (x >= RAD + 1) ? pref[PADI(x - RAD - 1)] : 0.f;
            bx[k] = hi - lo;
        }
#pragma unroll
        for (int j = 0; j < 4; j++) {
            float4 o;
            o.x = bx[4*j+0]; o.y = bx[4*j+1]; o.z = bx[4*j+2]; o.w = bx[4*j+3];
            ((float4*)(outp + cb))[j] = o;
        }
        __syncwarp();
    };

    { float a = 0.f;
#pragma unroll
      for (int k = 0; k < 16; k++) { a += gv[k]; lp[k] = a; } }
    scan_store(g_hsum[0] + rowOff);
    { float a = 0.f;
#pragma unroll
      for (int k = 0; k < 16; k++) { a += gv[k] * gv[k]; lp[k] = a; } }
    scan_store(g_hsum[1] + rowOff);

    const float* pc[3] = { p0, p1, p2 };
    const int qp[3] = { 2, 3, 4 };
    const int qip[3] = { 5, 6, 7 };
#pragma unroll
    for (int c = 0; c < 3; c++) {
#pragma unroll
        for (int j = 0; j < 4; j++) {
            float4 v = ((const float4*)(pc[c] + cb))[j];
            pv[4*j+0] = v.x; pv[4*j+1] = v.y; pv[4*j+2] = v.z; pv[4*j+3] = v.w;
        }
        { float a = 0.f;
#pragma unroll
          for (int k = 0; k < 16; k++) { a += pv[k]; lp[k] = a; } }
        scan_store(g_hsum[qp[c]] + rowOff);
        { float a = 0.f;
#pragma unroll
          for (int k = 0; k < 16; k++) { a += gv[k] * pv[k]; lp[k] = a; } }
        scan_store(g_hsum[qip[c]] + rowOff);
    }
}

// ============================================================================
// K2 (fused vertical+horizontal on a,b): R6 shape (256 thr, float2, full row),
// SEGV=8 -> 512 blocks, chain halved. 2 barriers/row, slide prefetch.
// grid (HH/SEGV, BATCH) = (64, 8)
// ============================================================================
__global__ __launch_bounds__(256) void k_vh() {
    const int tid  = threadIdx.x;
    const int warp = tid >> 5;
    const int lane = tid & 31;
    const int r0 = blockIdx.x * SEGV;
    const int b  = blockIdx.y;
    const size_t base = (size_t)b * (PLANE / 2) + tid;

    __shared__ float s_pref[2][6][WW];   // 24 KB
    __shared__ float s_wtot[2][6][8];

    float2 s[8];
#pragma unroll
    for (int q = 0; q < 8; q++) { s[q].x = 0.f; s[q].y = 0.f; }

    const int jstart = (r0 - RAD < 0) ? 0 : (r0 - RAD);
    const int jend   = (r0 + RAD > HH - 1) ? (HH - 1) : (r0 + RAD);
#pragma unroll 4
    for (int j = jstart; j <= jend; j++) {
        const size_t off = base + (size_t)j * W2;
#pragma unroll
        for (int q = 0; q < 8; q++) {
            float2 v = ((const float2*)g_hsum[q])[off];
            s[q].x += v.x; s[q].y += v.y;
        }
    }

    for (int i = 0; i < SEGV; i++) {
        const int row = r0 + i;
        const size_t off = base + (size_t)row * W2;
        const int bu = i & 1;

        const int lead  = row + RAD + 1;
        const int trail = row - RAD;
        const bool hl = lead < HH;
        const bool ht = trail >= 0;
        float2 ldv[8], trv[8];
        if (hl) {
            const size_t lo = base + (size_t)lead * W2;
#pragma unroll
            for (int q = 0; q < 8; q++) ldv[q] = ((const float2*)g_hsum[q])[lo];
        }
        if (ht) {
            const size_t to = base + (size_t)trail * W2;
#pragma unroll
            for (int q = 0; q < 8; q++) trv[q] = ((const float2*)g_hsum[q])[to];
        }

        float2 ab[6];
        {
            float mIx = s[0].x * INV_K2, mIy = s[0].y * INV_K2;
            float cIx = s[1].x * INV_K2, cIy = s[1].y * INV_K2;
            float ivx = 1.f / (cIx - mIx * mIx + EPSV);
            float ivy = 1.f / (cIy - mIy * mIy + EPSV);
#pragma unroll
            for (int c = 0; c < 3; c++) {
                float mpx  = s[2 + c].x * INV_K2, mpy  = s[2 + c].y * INV_K2;
                float cIpx = s[5 + c].x * INV_K2, cIpy = s[5 + c].y * INV_K2;
                float ax = (cIpx - mIx * mpx) * ivx;
                float ay = (cIpy - mIy * mpy) * ivy;
                ab[c].x = ax;                 ab[c].y = ay;
                ab[3 + c].x = mpx - ax * mIx; ab[3 + c].y = mpy - ay * mIy;
            }
        }

        float tq[6], wv[6];
#pragma unroll
        for (int q = 0; q < 6; q++) {
            tq[q] = ab[q].x + ab[q].y;
            wv[q] = iscan(tq[q], lane);
            if (lane == 31) s_wtot[bu][q][warp] = wv[q];
        }
        __syncthreads();
#pragma unroll
        for (int q = 0; q < 6; q++) {
            float carry = 0.f;
#pragma unroll
            for (int w = 0; w < 7; w++) if (w < warp) carry += s_wtot[bu][q][w];
            float ex = wv[q] - tq[q] + carry;
            float2 pr;
            pr.x = ex + ab[q].x;
            pr.y = pr.x + ab[q].y;
            ((float2*)s_pref[bu][q])[tid] = pr;
        }
        __syncthreads();

        const int x0 = 2 * tid, x1 = x0 + 1;
        const int h0 = (x0 + RAD > WW - 1) ? (WW - 1) : (x0 + RAD);
        const int h1 = (x1 + RAD > WW - 1) ? (WW - 1) : (x1 + RAD);
#pragma unroll
        for (int q = 0; q < 6; q++) {
            float lo0 = (x0 >= RAD + 1) ? s_pref[bu][q][x0 - RAD - 1] : 0.f;
            float lo1 = (x1 >= RAD + 1) ? s_pref[bu][q][x1 - RAD - 1] : 0.f;
            float2 o;
            o.x = s_pref[bu][q][h0] - lo0;
            o.y = s_pref[bu][q][h1] - lo1;
            ((float2*)g_hsum2[q])[off] = o;
        }

        if (hl) {
#pragma unroll
            for (int q = 0; q < 8; q++) { s[q].x += ldv[q].x; s[q].y += ldv[q].y; }
        }
        if (ht) {
#pragma unroll
            for (int q = 0; q < 8; q++) { s[q].x -= trv[q].x; s[q].y -= trv[q].y; }
        }
    }
}

// ============================================================================
// K3: vertical running sums on hsum2 (float4/thread), per channel, fused
// output. [R6 config] grid (1, HH/SEG, BATCH*3) = 768 blocks.
// ============================================================================
__global__ __launch_bounds__(128) void k_v2(float* __restrict__ out) {
    const int t  = threadIdx.x;
    const int zc = blockIdx.z;
    const int b  = zc / 3;
    const int c  = zc - b * 3;
    const int r0 = blockIdx.y * SEG;
    const size_t base = (size_t)b * (PLANE / 4) + t;

    const float4* __restrict__ pa = (const float4*)g_hsum2[c];
    const float4* __restrict__ pb = (const float4*)g_hsum2[3 + c];
    const float4* __restrict__ pg = (const float4*)g_gray;
    float4* __restrict__ po = (float4*)(out + (size_t)zc * PLANE);

    float4 sa = make_float4(0.f, 0.f, 0.f, 0.f);
    float4 sb = make_float4(0.f, 0.f, 0.f, 0.f);

    const int jstart = (r0 - RAD < 0) ? 0 : (r0 - RAD);
#pragma unroll 4
    for (int j = jstart; j <= r0 + RAD; j++) {
        const size_t off = base + (size_t)j * W4;
        float4 va = pa[off], vb = pb[off];
        sa.x += va.x; sa.y += va.y; sa.z += va.z; sa.w += va.w;
        sb.x += vb.x; sb.y += vb.y; sb.z += vb.z; sb.w += vb.w;
    }

#pragma unroll 4
    for (int i = 0; i < SEG; i++) {
        const int row = r0 + i;
        const size_t off = base + (size_t)row * W4;

        const int lead  = row + RAD + 1;
        const int trail = row - RAD;
        const bool hl = lead < HH;
        const bool ht = trail >= 0;
        float4 la, lb, ta, tb;
        if (hl) {
            const size_t lo = base + (size_t)lead * W4;
            la = pa[lo]; lb = pb[lo];
        }
        if (ht) {
            const size_t to = base + (size_t)trail * W4;
            ta = pa[to]; tb = pb[to];
        }

        const float4 gr = pg[off];
        float4 o;
        o.x = (sa.x * INV_K2) * gr.x + sb.x * INV_K2;
        o.y = (sa.y * INV_K2) * gr.y + sb.y * INV_K2;
        o.z = (sa.z * INV_K2) * gr.z + sb.z * INV_K2;
        o.w = (sa.w * INV_K2) * gr.w + sb.w * INV_K2;
        po[(size_t)row * W4 + t] = o;

        if (hl) {
            sa.x += la.x; sa.y += la.y; sa.z += la.z; sa.w += la.w;
            sb.x += lb.x; sb.y += lb.y; sb.z += lb.z; sb.w += lb.w;
        }
        if (ht) {
            sa.x -= ta.x; sa.y -= ta.y; sa.z -= ta.z; sa.w -= ta.w;
            sb.x -= tb.x; sb.y -= tb.y; sb.z -= tb.z; sb.w -= tb.w;
        }
    }
}

// ============================================================================
extern "C" void kernel_launch(void* const* d_in, const int* in_sizes, int n_in,
                              void* d_out, int out_size) {
    const float* guide = (const float*)d_in[0];
    const float* input = (const float*)d_in[1];
    float* out = (float*)d_out;

    k_h1<<<BATCH * HH / 4, 128>>>(guide, input);
    k_vh<<<dim3(HH / SEGV, BATCH), 256>>>();
    k_v2<<<dim3(1, HH / SEG, BATCH * 3), 128>>>(out);
}

// round 11
// speedup vs baseline: 1.4794x; 1.2286x over previous
#include <cuda_runtime.h>
#include <cuda_fp16.h>

#define BATCH 8
#define HH 512
#define WW 512
#define W2 (WW / 2)
#define PLANE (HH * WW)
#define NP (BATCH * PLANE)
#define RAD 15
#define INV_K2 (1.0f / 961.0f)
#define EPSV 1e-6f
#define SEG 16        // rows per vertical segment (k_v2)  [R6 optimum]
#define SEGV 16       // rows per vertical segment (k_vh)  [R6 optimum, both directions tested]
#define SPAD 544
#define PADI(i) ((i) + ((i) >> 4))

// -------- scratch (device globals) --------
// stage-1 quantities (fp32 — var cancellation amplifies errors ~30x):
// 0=I, 1=I*I, 2..4=p_c, 5..7=I*p_c
__device__ float  g_hsum[8][NP];   // 64 MB
// final-stage planes (fp16 — errors enter output linearly):
__device__ __half g_gray[NP];      // 4 MB
__device__ __half g_hsum2[6][NP];  // 24 MB

__device__ __forceinline__ float iscan(float v, int lane) {
#pragma unroll
    for (int o = 1; o < 32; o <<= 1) {
        float n = __shfl_up_sync(0xffffffffu, v, o);
        if (lane >= o) v += n;
    }
    return v;
}

// load 4 consecutive halves (8B aligned) as float4
__device__ __forceinline__ float4 ldh4(const __half* p, int idx) {
    uint2 r = *reinterpret_cast<const uint2*>(p + idx);
    __half2 h0 = *reinterpret_cast<__half2*>(&r.x);
    __half2 h1 = *reinterpret_cast<__half2*>(&r.y);
    float2 f0 = __half22float2(h0), f1 = __half22float2(h1);
    return make_float4(f0.x, f0.y, f1.x, f1.y);
}

// ============================================================================
// K1: horizontal pass, chunk-local scan, register-direct loads, COALESCED
// ST.32 box-sum stores (R6 — proven). gray persisted as fp16.
// 1 warp/row, 4 rows/block.
// ============================================================================
__global__ __launch_bounds__(128) void k_h1(const float* __restrict__ guide,
                                            const float* __restrict__ input) {
    const int warp = threadIdx.x >> 5;
    const int lane = threadIdx.x & 31;
    const int grow = blockIdx.x * 4 + warp;
    const int b = grow >> 9;
    const int r = grow & 511;

    const float* gR = guide + ((size_t)(b * 3 + 0) * HH + r) * WW;
    const float* gG = guide + ((size_t)(b * 3 + 1) * HH + r) * WW;
    const float* gB = guide + ((size_t)(b * 3 + 2) * HH + r) * WW;
    const float* p0 = input + ((size_t)(b * 3 + 0) * HH + r) * WW;
    const float* p1 = input + ((size_t)(b * 3 + 1) * HH + r) * WW;
    const float* p2 = input + ((size_t)(b * 3 + 2) * HH + r) * WW;

    __shared__ float sp[4][SPAD];
    float* pref = sp[warp];

    const size_t rowOff = (size_t)grow * WW;
    const int cb = lane * 16;

    float gv[16], pv[16], lp[16];

#pragma unroll
    for (int j = 0; j < 4; j++) {
        float4 rv = ((const float4*)(gR + cb))[j];
        float4 gg = ((const float4*)(gG + cb))[j];
        float4 bv = ((const float4*)(gB + cb))[j];
        gv[4*j+0] = 0.299f * rv.x + 0.587f * gg.x + 0.114f * bv.x;
        gv[4*j+1] = 0.299f * rv.y + 0.587f * gg.y + 0.114f * bv.y;
        gv[4*j+2] = 0.299f * rv.z + 0.587f * gg.z + 0.114f * bv.z;
        gv[4*j+3] = 0.299f * rv.w + 0.587f * gg.w + 0.114f * bv.w;
    }
    // persist gray as fp16 (16 halves = 32B per chunk, two 16B stores)
    {
        __half2 h[8];
#pragma unroll
        for (int j = 0; j < 8; j++) h[j] = __floats2half2_rn(gv[2*j], gv[2*j+1]);
        uint4* dst = reinterpret_cast<uint4*>(g_gray + rowOff + cb);
        dst[0] = *reinterpret_cast<uint4*>(&h[0]);
        dst[1] = *reinterpret_cast<uint4*>(&h[4]);
    }

    auto scan_store = [&](float* __restrict__ outp) {
        float tot = lp[15];
        float ex = iscan(tot, lane) - tot;
#pragma unroll
        for (int k = 0; k < 16; k++) pref[PADI(cb + k)] = ex + lp[k];
        __syncwarp();
#pragma unroll
        for (int i = 0; i < 16; i++) {
            int x = i * 32 + lane;
            int hx = (x + RAD > WW - 1) ? (WW - 1) : (x + RAD);
            float hi = pref[PADI(hx)];
            float lo = (x >= RAD + 1) ? pref[PADI(x - RAD - 1)] : 0.f;
            outp[x] = hi - lo;
        }
        __syncwarp();
    };

    { float a = 0.f;
#pragma unroll
      for (int k = 0; k < 16; k++) { a += gv[k]; lp[k] = a; } }
    scan_store(g_hsum[0] + rowOff);
    { float a = 0.f;
#pragma unroll
      for (int k = 0; k < 16; k++) { a += gv[k] * gv[k]; lp[k] = a; } }
    scan_store(g_hsum[1] + rowOff);

    const float* pc[3] = { p0, p1, p2 };
    const int qp[3] = { 2, 3, 4 };
    const int qip[3] = { 5, 6, 7 };
#pragma unroll
    for (int c = 0; c < 3; c++) {
#pragma unroll
        for (int j = 0; j < 4; j++) {
            float4 v = ((const float4*)(pc[c] + cb))[j];
            pv[4*j+0] = v.x; pv[4*j+1] = v.y; pv[4*j+2] = v.z; pv[4*j+3] = v.w;
        }
        { float a = 0.f;
#pragma unroll
          for (int k = 0; k < 16; k++) { a += pv[k]; lp[k] = a; } }
        scan_store(g_hsum[qp[c]] + rowOff);
        { float a = 0.f;
#pragma unroll
          for (int k = 0; k < 16; k++) { a += gv[k] * pv[k]; lp[k] = a; } }
        scan_store(g_hsum[qip[c]] + rowOff);
    }
}

// ============================================================================
// K2 (fused vertical+horizontal on a,b): R6 shape — 256 thr, float2/thread,
// SEGV=16, 2 barriers/row, double-buffered smem, slide prefetch.
// hsum2 written as fp16 (half2 per thread per plane). grid (32, 8).
// ============================================================================
__global__ __launch_bounds__(256) void k_vh() {
    const int tid  = threadIdx.x;
    const int warp = tid >> 5;
    const int lane = tid & 31;
    const int r0 = blockIdx.x * SEGV;
    const int b  = blockIdx.y;
    const size_t base = (size_t)b * (PLANE / 2) + tid;

    __shared__ float s_pref[2][6][WW];   // 24 KB
    __shared__ float s_wtot[2][6][8];

    float2 s[8];
#pragma unroll
    for (int q = 0; q < 8; q++) { s[q].x = 0.f; s[q].y = 0.f; }

    const int jstart = (r0 - RAD < 0) ? 0 : (r0 - RAD);
#pragma unroll 4
    for (int j = jstart; j <= r0 + RAD; j++) {
        const size_t off = base + (size_t)j * W2;
#pragma unroll
        for (int q = 0; q < 8; q++) {
            float2 v = ((const float2*)g_hsum[q])[off];
            s[q].x += v.x; s[q].y += v.y;
        }
    }

    for (int i = 0; i < SEGV; i++) {
        const int row = r0 + i;
        const size_t off = base + (size_t)row * W2;
        const int bu = i & 1;

        const int lead  = row + RAD + 1;
        const int trail = row - RAD;
        const bool hl = lead < HH;
        const bool ht = trail >= 0;
        float2 ldv[8], trv[8];
        if (hl) {
            const size_t lo = base + (size_t)lead * W2;
#pragma unroll
            for (int q = 0; q < 8; q++) ldv[q] = ((const float2*)g_hsum[q])[lo];
        }
        if (ht) {
            const size_t to = base + (size_t)trail * W2;
#pragma unroll
            for (int q = 0; q < 8; q++) trv[q] = ((const float2*)g_hsum[q])[to];
        }

        float2 ab[6];
        {
            float mIx = s[0].x * INV_K2, mIy = s[0].y * INV_K2;
            float cIx = s[1].x * INV_K2, cIy = s[1].y * INV_K2;
            float ivx = 1.f / (cIx - mIx * mIx + EPSV);
            float ivy = 1.f / (cIy - mIy * mIy + EPSV);
#pragma unroll
            for (int c = 0; c < 3; c++) {
                float mpx  = s[2 + c].x * INV_K2, mpy  = s[2 + c].y * INV_K2;
                float cIpx = s[5 + c].x * INV_K2, cIpy = s[5 + c].y * INV_K2;
                float ax = (cIpx - mIx * mpx) * ivx;
                float ay = (cIpy - mIy * mpy) * ivy;
                ab[c].x = ax;                 ab[c].y = ay;
                ab[3 + c].x = mpx - ax * mIx; ab[3 + c].y = mpy - ay * mIy;
            }
        }

        float tq[6], wv[6];
#pragma unroll
        for (int q = 0; q < 6; q++) {
            tq[q] = ab[q].x + ab[q].y;
            wv[q] = iscan(tq[q], lane);
            if (lane == 31) s_wtot[bu][q][warp] = wv[q];
        }
        __syncthreads();
#pragma unroll
        for (int q = 0; q < 6; q++) {
            float carry = 0.f;
#pragma unroll
            for (int w = 0; w < 7; w++) if (w < warp) carry += s_wtot[bu][q][w];
            float ex = wv[q] - tq[q] + carry;
            float2 pr;
            pr.x = ex + ab[q].x;
            pr.y = pr.x + ab[q].y;
            ((float2*)s_pref[bu][q])[tid] = pr;
        }
        __syncthreads();

        const int x0 = 2 * tid, x1 = x0 + 1;
        const int h0 = (x0 + RAD > WW - 1) ? (WW - 1) : (x0 + RAD);
        const int h1 = (x1 + RAD > WW - 1) ? (WW - 1) : (x1 + RAD);
#pragma unroll
        for (int q = 0; q < 6; q++) {
            float lo0 = (x0 >= RAD + 1) ? s_pref[bu][q][x0 - RAD - 1] : 0.f;
            float lo1 = (x1 >= RAD + 1) ? s_pref[bu][q][x1 - RAD - 1] : 0.f;
            __half2 hv = __floats2half2_rn(s_pref[bu][q][h0] - lo0,
                                           s_pref[bu][q][h1] - lo1);
            ((__half2*)g_hsum2[q])[off] = hv;
        }

        if (hl) {
#pragma unroll
            for (int q = 0; q < 8; q++) { s[q].x += ldv[q].x; s[q].y += ldv[q].y; }
        }
        if (ht) {
#pragma unroll
            for (int q = 0; q < 8; q++) { s[q].x -= trv[q].x; s[q].y -= trv[q].y; }
        }
    }
}

// ============================================================================
// K3: vertical running sums on fp16 hsum2 (4 cols/thread, fp32 accumulators),
// per channel, fused output. grid (1, HH/SEG, BATCH*3) = 768 blocks.
// ============================================================================
__global__ __launch_bounds__(128) void k_v2(float* __restrict__ out) {
    const int t  = threadIdx.x;                  // 4-col group index
    const int zc = blockIdx.z;
    const int b  = zc / 3;
    const int c  = zc - b * 3;
    const int r0 = blockIdx.y * SEG;
    const int baseh = b * PLANE + 4 * t;         // half index of first col

    const __half* __restrict__ pa = g_hsum2[c];
    const __half* __restrict__ pb = g_hsum2[3 + c];
    const __half* __restrict__ pg = g_gray;
    float4* __restrict__ po = (float4*)(out + (size_t)zc * PLANE);

    float4 sa = make_float4(0.f, 0.f, 0.f, 0.f);
    float4 sb = make_float4(0.f, 0.f, 0.f, 0.f);

    const int jstart = (r0 - RAD < 0) ? 0 : (r0 - RAD);
#pragma unroll 4
    for (int j = jstart; j <= r0 + RAD; j++) {
        const int off = baseh + j * WW;
        float4 va = ldh4(pa, off), vb = ldh4(pb, off);
        sa.x += va.x; sa.y += va.y; sa.z += va.z; sa.w += va.w;
        sb.x += vb.x; sb.y += vb.y; sb.z += vb.z; sb.w += vb.w;
    }

#pragma unroll 4
    for (int i = 0; i < SEG; i++) {
        const int row = r0 + i;
        const int off = baseh + row * WW;

        const int lead  = row + RAD + 1;
        const int trail = row - RAD;
        const bool hl = lead < HH;
        const bool ht = trail >= 0;
        float4 la, lb, ta, tb;
        if (hl) {
            const int lo = baseh + lead * WW;
            la = ldh4(pa, lo); lb = ldh4(pb, lo);
        }
        if (ht) {
            const int to = baseh + trail * WW;
            ta = ldh4(pa, to); tb = ldh4(pb, to);
        }

        const float4 gr = ldh4(pg, off);
        float4 o;
        o.x = (sa.x * INV_K2) * gr.x + sb.x * INV_K2;
        o.y = (sa.y * INV_K2) * gr.y + sb.y * INV_K2;
        o.z = (sa.z * INV_K2) * gr.z + sb.z * INV_K2;
        o.w = (sa.w * INV_K2) * gr.w + sb.w * INV_K2;
        po[(size_t)row * (WW / 4) + t] = o;

        if (hl) {
            sa.x += la.x; sa.y += la.y; sa.z += la.z; sa.w += la.w;
            sb.x += lb.x; sb.y += lb.y; sb.z += lb.z; sb.w += lb.w;
        }
        if (ht) {
            sa.x -= ta.x; sa.y -= ta.y; sa.z -= ta.z; sa.w -= ta.w;
            sb.x -= tb.x; sb.y -= tb.y; sb.z -= tb.z; sb.w -= tb.w;
        }
    }
}

// ============================================================================
extern "C" void kernel_launch(void* const* d_in, const int* in_sizes, int n_in,
                              void* d_out, int out_size) {
    const float* guide = (const float*)d_in[0];
    const float* input = (const float*)d_in[1];
    float* out = (float*)d_out;

    k_h1<<<BATCH * HH / 4, 128>>>(guide, input);
    k_vh<<<dim3(HH / SEGV, BATCH), 256>>>();
    k_v2<<<dim3(1, HH / SEG, BATCH * 3), 128>>>(out);
}

// round 12
// speedup vs baseline: 1.4800x; 1.0004x over previous
#include <cuda_runtime.h>
#include <cuda_fp16.h>

#define BATCH 8
#define HH 512
#define WW 512
#define W2 (WW / 2)
#define PLANE (HH * WW)
#define NP (BATCH * PLANE)
#define RAD 15
#define INV_K2 (1.0f / 961.0f)
#define EPSV 1e-6f
#define SEG 16        // rows per vertical segment (k_v2)
#define SEGV 16       // rows per vertical segment (k_vh)
#define SPAD 544
#define PADI(i) ((i) + ((i) >> 4))

// -------- scratch (device globals) --------
// stage-1 horizontal box sums, fp16 (fp32 accumulation everywhere downstream):
// 0=I, 1=I*I, 2..4=p_c, 5..7=I*p_c
__device__ __half g_hsum[8][NP];   // 32 MB
__device__ __half g_gray[NP];      // 4 MB
__device__ __half g_hsum2[6][NP];  // 24 MB

__device__ __forceinline__ float iscan(float v, int lane) {
#pragma unroll
    for (int o = 1; o < 32; o <<= 1) {
        float n = __shfl_up_sync(0xffffffffu, v, o);
        if (lane >= o) v += n;
    }
    return v;
}

// load 4 consecutive halves (8B aligned) as float4
__device__ __forceinline__ float4 ldh4(const __half* p, int idx) {
    uint2 r = *reinterpret_cast<const uint2*>(p + idx);
    __half2 h0 = *reinterpret_cast<__half2*>(&r.x);
    __half2 h1 = *reinterpret_cast<__half2*>(&r.y);
    float2 f0 = __half22float2(h0), f1 = __half22float2(h1);
    return make_float4(f0.x, f0.y, f1.x, f1.y);
}

// ============================================================================
// K1: horizontal pass, chunk-local scan, register-direct loads, coalesced
// fp16 box-sum stores. 1 warp/row, 4 rows/block.
// ============================================================================
__global__ __launch_bounds__(128) void k_h1(const float* __restrict__ guide,
                                            const float* __restrict__ input) {
    const int warp = threadIdx.x >> 5;
    const int lane = threadIdx.x & 31;
    const int grow = blockIdx.x * 4 + warp;
    const int b = grow >> 9;
    const int r = grow & 511;

    const float* gR = guide + ((size_t)(b * 3 + 0) * HH + r) * WW;
    const float* gG = guide + ((size_t)(b * 3 + 1) * HH + r) * WW;
    const float* gB = guide + ((size_t)(b * 3 + 2) * HH + r) * WW;
    const float* p0 = input + ((size_t)(b * 3 + 0) * HH + r) * WW;
    const float* p1 = input + ((size_t)(b * 3 + 1) * HH + r) * WW;
    const float* p2 = input + ((size_t)(b * 3 + 2) * HH + r) * WW;

    __shared__ float sp[4][SPAD];
    float* pref = sp[warp];

    const size_t rowOff = (size_t)grow * WW;
    const int cb = lane * 16;

    float gv[16], pv[16], lp[16];

#pragma unroll
    for (int j = 0; j < 4; j++) {
        float4 rv = ((const float4*)(gR + cb))[j];
        float4 gg = ((const float4*)(gG + cb))[j];
        float4 bv = ((const float4*)(gB + cb))[j];
        gv[4*j+0] = 0.299f * rv.x + 0.587f * gg.x + 0.114f * bv.x;
        gv[4*j+1] = 0.299f * rv.y + 0.587f * gg.y + 0.114f * bv.y;
        gv[4*j+2] = 0.299f * rv.z + 0.587f * gg.z + 0.114f * bv.z;
        gv[4*j+3] = 0.299f * rv.w + 0.587f * gg.w + 0.114f * bv.w;
    }
    // persist gray as fp16 (two 16B stores per chunk)
    {
        __half2 h[8];
#pragma unroll
        for (int j = 0; j < 8; j++) h[j] = __floats2half2_rn(gv[2*j], gv[2*j+1]);
        uint4* dst = reinterpret_cast<uint4*>(g_gray + rowOff + cb);
        dst[0] = *reinterpret_cast<uint4*>(&h[0]);
        dst[1] = *reinterpret_cast<uint4*>(&h[4]);
    }

    auto scan_store = [&](__half* __restrict__ outp) {
        float tot = lp[15];
        float ex = iscan(tot, lane) - tot;
#pragma unroll
        for (int k = 0; k < 16; k++) pref[PADI(cb + k)] = ex + lp[k];
        __syncwarp();
#pragma unroll
        for (int i = 0; i < 16; i++) {
            int x = i * 32 + lane;
            int hx = (x + RAD > WW - 1) ? (WW - 1) : (x + RAD);
            float hi = pref[PADI(hx)];
            float lo = (x >= RAD + 1) ? pref[PADI(x - RAD - 1)] : 0.f;
            outp[x] = __float2half_rn(hi - lo);
        }
        __syncwarp();
    };

    { float a = 0.f;
#pragma unroll
      for (int k = 0; k < 16; k++) { a += gv[k]; lp[k] = a; } }
    scan_store(g_hsum[0] + rowOff);
    { float a = 0.f;
#pragma unroll
      for (int k = 0; k < 16; k++) { a += gv[k] * gv[k]; lp[k] = a; } }
    scan_store(g_hsum[1] + rowOff);

    const float* pc[3] = { p0, p1, p2 };
    const int qp[3] = { 2, 3, 4 };
    const int qip[3] = { 5, 6, 7 };
#pragma unroll
    for (int c = 0; c < 3; c++) {
#pragma unroll
        for (int j = 0; j < 4; j++) {
            float4 v = ((const float4*)(pc[c] + cb))[j];
            pv[4*j+0] = v.x; pv[4*j+1] = v.y; pv[4*j+2] = v.z; pv[4*j+3] = v.w;
        }
        { float a = 0.f;
#pragma unroll
          for (int k = 0; k < 16; k++) { a += pv[k]; lp[k] = a; } }
        scan_store(g_hsum[qp[c]] + rowOff);
        { float a = 0.f;
#pragma unroll
          for (int k = 0; k < 16; k++) { a += gv[k] * pv[k]; lp[k] = a; } }
        scan_store(g_hsum[qip[c]] + rowOff);
    }
}

// ============================================================================
// K2 (fused vertical+horizontal on a,b): 256 thr, 2 cols/thread (half2 loads,
// fp32 accumulators), SEGV=16, 2 barriers/row, slide prefetch. grid (32, 8).
// ============================================================================
__global__ __launch_bounds__(256) void k_vh() {
    const int tid  = threadIdx.x;
    const int warp = tid >> 5;
    const int lane = tid & 31;
    const int r0 = blockIdx.x * SEGV;
    const int b  = blockIdx.y;
    const int base = b * (PLANE / 2) + tid;   // half2 index

    __shared__ float s_pref[2][6][WW];   // 24 KB
    __shared__ float s_wtot[2][6][8];

    float2 s[8];
#pragma unroll
    for (int q = 0; q < 8; q++) { s[q].x = 0.f; s[q].y = 0.f; }

    const int jstart = (r0 - RAD < 0) ? 0 : (r0 - RAD);
#pragma unroll 4
    for (int j = jstart; j <= r0 + RAD; j++) {
        const int off = base + j * W2;
#pragma unroll
        for (int q = 0; q < 8; q++) {
            float2 v = __half22float2(((const __half2*)g_hsum[q])[off]);
            s[q].x += v.x; s[q].y += v.y;
        }
    }

    for (int i = 0; i < SEGV; i++) {
        const int row = r0 + i;
        const int off = base + row * W2;
        const int bu = i & 1;

        const int lead  = row + RAD + 1;
        const int trail = row - RAD;
        const bool hl = lead < HH;
        const bool ht = trail >= 0;
        float2 ldv[8], trv[8];
        if (hl) {
            const int lo = base + lead * W2;
#pragma unroll
            for (int q = 0; q < 8; q++)
                ldv[q] = __half22float2(((const __half2*)g_hsum[q])[lo]);
        }
        if (ht) {
            const int to = base + trail * W2;
#pragma unroll
            for (int q = 0; q < 8; q++)
                trv[q] = __half22float2(((const __half2*)g_hsum[q])[to]);
        }

        float2 ab[6];
        {
            float mIx = s[0].x * INV_K2, mIy = s[0].y * INV_K2;
            float cIx = s[1].x * INV_K2, cIy = s[1].y * INV_K2;
            float ivx = 1.f / (cIx - mIx * mIx + EPSV);
            float ivy = 1.f / (cIy - mIy * mIy + EPSV);
#pragma unroll
            for (int c = 0; c < 3; c++) {
                float mpx  = s[2 + c].x * INV_K2, mpy  = s[2 + c].y * INV_K2;
                float cIpx = s[5 + c].x * INV_K2, cIpy = s[5 + c].y * INV_K2;
                float ax = (cIpx - mIx * mpx) * ivx;
                float ay = (cIpy - mIy * mpy) * ivy;
                ab[c].x = ax;                 ab[c].y = ay;
                ab[3 + c].x = mpx - ax * mIx; ab[3 + c].y = mpy - ay * mIy;
            }
        }

        float tq[6], wv[6];
#pragma unroll
        for (int q = 0; q < 6; q++) {
            tq[q] = ab[q].x + ab[q].y;
            wv[q] = iscan(tq[q], lane);
            if (lane == 31) s_wtot[bu][q][warp] = wv[q];
        }
        __syncthreads();
#pragma unroll
        for (int q = 0; q < 6; q++) {
            float carry = 0.f;
#pragma unroll
            for (int w = 0; w < 7; w++) if (w < warp) carry += s_wtot[bu][q][w];
            float ex = wv[q] - tq[q] + carry;
            float2 pr;
            pr.x = ex + ab[q].x;
            pr.y = pr.x + ab[q].y;
            ((float2*)s_pref[bu][q])[tid] = pr;
        }
        __syncthreads();

        const int x0 = 2 * tid, x1 = x0 + 1;
        const int h0 = (x0 + RAD > WW - 1) ? (WW - 1) : (x0 + RAD);
        const int h1 = (x1 + RAD > WW - 1) ? (WW - 1) : (x1 + RAD);
#pragma unroll
        for (int q = 0; q < 6; q++) {
            float lo0 = (x0 >= RAD + 1) ? s_pref[bu][q][x0 - RAD - 1] : 0.f;
            float lo1 = (x1 >= RAD + 1) ? s_pref[bu][q][x1 - RAD - 1] : 0.f;
            __half2 hv = __floats2half2_rn(s_pref[bu][q][h0] - lo0,
                                           s_pref[bu][q][h1] - lo1);
            ((__half2*)g_hsum2[q])[off] = hv;
        }

        if (hl) {
#pragma unroll
            for (int q = 0; q < 8; q++) { s[q].x += ldv[q].x; s[q].y += ldv[q].y; }
        }
        if (ht) {
#pragma unroll
            for (int q = 0; q < 8; q++) { s[q].x -= trv[q].x; s[q].y -= trv[q].y; }
        }
    }
}

// ============================================================================
// K3: vertical running sums on fp16 hsum2 (4 cols/thread, fp32 accumulators),
// per channel, fused output. grid (1, HH/SEG, BATCH*3) = 768 blocks.
// ============================================================================
__global__ __launch_bounds__(128) void k_v2(float* __restrict__ out) {
    const int t  = threadIdx.x;
    const int zc = blockIdx.z;
    const int b  = zc / 3;
    const int c  = zc - b * 3;
    const int r0 = blockIdx.y * SEG;
    const int baseh = b * PLANE + 4 * t;

    const __half* __restrict__ pa = g_hsum2[c];
    const __half* __restrict__ pb = g_hsum2[3 + c];
    const __half* __restrict__ pg = g_gray;
    float4* __restrict__ po = (float4*)(out + (size_t)zc * PLANE);

    float4 sa = make_float4(0.f, 0.f, 0.f, 0.f);
    float4 sb = make_float4(0.f, 0.f, 0.f, 0.f);

    const int jstart = (r0 - RAD < 0) ? 0 : (r0 - RAD);
#pragma unroll 4
    for (int j = jstart; j <= r0 + RAD; j++) {
        const int off = baseh + j * WW;
        float4 va = ldh4(pa, off), vb = ldh4(pb, off);
        sa.x += va.x; sa.y += va.y; sa.z += va.z; sa.w += va.w;
        sb.x += vb.x; sb.y += vb.y; sb.z += vb.z; sb.w += vb.w;
    }

#pragma unroll 4
    for (int i = 0; i < SEG; i++) {
        const int row = r0 + i;
        const int off = baseh + row * WW;

        const int lead  = row + RAD + 1;
        const int trail = row - RAD;
        const bool hl = lead < HH;
        const bool ht = trail >= 0;
        float4 la, lb, ta, tb;
        if (hl) {
            const int lo = baseh + lead * WW;
            la = ldh4(pa, lo); lb = ldh4(pb, lo);
        }
        if (ht) {
            const int to = baseh + trail * WW;
            ta = ldh4(pa, to); tb = ldh4(pb, to);
        }

        const float4 gr = ldh4(pg, off);
        float4 o;
        o.x = (sa.x * INV_K2) * gr.x + sb.x * INV_K2;
        o.y = (sa.y * INV_K2) * gr.y + sb.y * INV_K2;
        o.z = (sa.z * INV_K2) * gr.z + sb.z * INV_K2;
        o.w = (sa.w * INV_K2) * gr.w + sb.w * INV_K2;
        po[(size_t)row * (WW / 4) + t] = o;

        if (hl) {
            sa.x += la.x; sa.y += la.y; sa.z += la.z; sa.w += la.w;
            sb.x += lb.x; sb.y += lb.y; sb.z += lb.z; sb.w += lb.w;
        }
        if (ht) {
            sa.x -= ta.x; sa.y -= ta.y; sa.z -= ta.z; sa.w -= ta.w;
            sb.x -= tb.x; sb.y -= tb.y; sb.z -= tb.z; sb.w -= tb.w;
        }
    }
}

// ============================================================================
extern "C" void kernel_launch(void* const* d_in, const int* in_sizes, int n_in,
                              void* d_out, int out_size) {
    const float* guide = (const float*)d_in[0];
    const float* input = (const float*)d_in[1];
    float* out = (float*)d_out;

    k_h1<<<BATCH * HH / 4, 128>>>(guide, input);
    k_vh<<<dim3(HH / SEGV, BATCH), 256>>>();
    k_v2<<<dim3(1, HH / SEG, BATCH * 3), 128>>>(out);
}